// round 2
// baseline (speedup 1.0000x reference)
#include <cuda_runtime.h>

#define NQ   12
#define DIM  4096
#define NL   6
#define TPB  256

typedef unsigned long long ull;

// padded smem slot to avoid bank conflicts in the stride-16 pass
#define SLOT(i) ((i) + ((i) >> 4))

struct Gate { float2 m00, m01, m10, m11; };

__device__ __forceinline__ ull pack2(float lo, float hi) {
    ull r;
    unsigned l = __float_as_uint(lo), h = __float_as_uint(hi);
    asm("mov.b64 %0, {%1, %2};" : "=l"(r) : "r"(l), "r"(h));
    return r;
}
__device__ __forceinline__ ull swp(ull a) {
    ull r;
    asm("{\n\t.reg .b32 lo, hi;\n\tmov.b64 {lo, hi}, %1;\n\tmov.b64 %0, {hi, lo};\n\t}"
        : "=l"(r) : "l"(a));
    return r;
}
__device__ __forceinline__ ull pmul(ull a, ull b) {
    ull r; asm("mul.rn.f32x2 %0, %1, %2;" : "=l"(r) : "l"(a), "l"(b));
    return r;
}
__device__ __forceinline__ ull pfma(ull a, ull b, ull c) {
    ull r; asm("fma.rn.f32x2 %0, %1, %2, %3;" : "=l"(r) : "l"(a), "l"(b), "l"(c));
    return r;
}

// Apply one complex 2x2 gate on register-resident amplitudes, pairing bit P.
// Packed layout: each v[j] = (re in low 32, im in high 32).
// n += m*v  ==  n = fma((m.re,m.re), v, n); n = fma((-m.im,m.im), swap(v), n)
template <int P>
__device__ __forceinline__ void apply_gate_pk(ull v[16], const float2* __restrict__ g) {
    ull c[8];
#pragma unroll
    for (int e = 0; e < 4; ++e) {
        const float2 m = g[e];
        c[2 * e]     = pack2(m.x, m.x);
        c[2 * e + 1] = pack2(-m.y, m.y);
    }
#pragma unroll
    for (int j0 = 0; j0 < 16; ++j0) {
        if (j0 & (1 << P)) continue;
        const int j1 = j0 | (1 << P);
        const ull a = v[j0], b = v[j1];
        const ull sa = swp(a), sb = swp(b);
        ull n0 = pmul(c[0], a);
        n0 = pfma(c[1], sa, n0);
        n0 = pfma(c[2], b, n0);
        n0 = pfma(c[3], sb, n0);
        ull n1 = pmul(c[4], a);
        n1 = pfma(c[5], sa, n1);
        n1 = pfma(c[6], b, n1);
        n1 = pfma(c[7], sb, n1);
        v[j0] = n0; v[j1] = n1;
    }
}

__global__ void __launch_bounds__(TPB, 3)
quantum_kernel(const float* __restrict__ x,
               const float* __restrict__ weights,
               const float* __restrict__ Wlin,
               const float* __restrict__ bias_p,
               float* __restrict__ out)
{
    __shared__ ull   psi[DIM + (DIM >> 4)];            // padded state, ~34 KB
    __shared__ Gate  gates[NL][NQ];                    // 2.3 KB
    __shared__ unsigned short srcHi[NL][64], srcLo[NL][64];   // CNOT-layer permutation (GF2 split)
    __shared__ float Phi[64], Plo[64], Thi[64], Tlo[64];
    __shared__ float cw[NQ], sw[NQ], Wv[NQ];
    __shared__ float red[TPB / 32];

    const int tid = threadIdx.x;
    const int bidx = blockIdx.x;

    // ---------- Phase 1: embedding trig, linear weights, gate matrices, CNOT tables ----------
    if (tid < NQ) {
        float h = 0.5f * x[bidx * NQ + tid];
        sincosf(h, &sw[tid], &cw[tid]);
        Wv[tid] = Wlin[tid];
    }
    for (int idx = tid; idx < NL * NQ; idx += TPB) {
        const int l = idx / NQ, w = idx % NQ;
        const float* wp = weights + (l * NQ + w) * 3;
        const float phi = wp[0], theta = wp[1], omega = wp[2];
        float st, ct; sincosf(0.5f * theta, &st, &ct);
        const float a = 0.5f * (phi + omega);
        const float b = 0.5f * (phi - omega);
        float sa, ca, sb, cb;
        sincosf(a, &sa, &ca);
        sincosf(b, &sb, &cb);
        Gate G;
        G.m00 = make_float2( ca * ct, -sa * ct);   // exp(-ia)*ct
        G.m01 = make_float2(-cb * st, -sb * st);   // -exp(+ib)*st
        G.m10 = make_float2( cb * st, -sb * st);   // conj(exp(+ib))*st
        G.m11 = make_float2( ca * ct,  sa * ct);   // conj(exp(-ia))*ct
        gates[l][w] = G;
    }
    for (int idx = tid; idx < NL * 128; idx += TPB) {
        const int l = idx >> 7, k = idx & 127;
        const int r = l % (NQ - 1) + 1;
        unsigned v = (k < 64) ? (unsigned)k : ((unsigned)(k - 64) << 6);
        // src = f_{w=0} o f_{w=1} o ... o f_{w=11}; apply w=11 first
        for (int w = NQ - 1; w >= 0; --w) {
            const int t = (w + r) % NQ;
            v ^= ((v >> (NQ - 1 - w)) & 1u) << (NQ - 1 - t);
        }
        if (k < 64) srcLo[l][k] = (unsigned short)v;
        else        srcHi[l][k - 64] = (unsigned short)v;
    }
    __syncthreads();

    // ---------- Phase 2: product-state init tables & expectation-sign tables ----------
    if (tid < 64) {
        const int j = tid;
        float ph = 1.f, pl = 1.f, th = 0.f, tl = 0.f;
#pragma unroll
        for (int w = 0; w < 6; ++w) {
            const int bh = (j >> (5 - w)) & 1;   // wires 0..5 -> hi bits
            ph *= bh ? sw[w] : cw[w];
            th += bh ? -Wv[w] : Wv[w];
            const int bl = (j >> (5 - w)) & 1;   // wires 6..11 -> lo bits
            pl *= bl ? sw[6 + w] : cw[6 + w];
            tl += bl ? -Wv[6 + w] : Wv[6 + w];
        }
        Phi[j] = ph; Plo[j] = pl; Thi[j] = th; Tlo[j] = tl;
    }
    __syncthreads();

    // ---------- Circuit: 6 layers x 3 grouped gate passes; CNOT perms fused into gathers ----------
    ull v[16];
    for (int l = 0; l < NL; ++l) {
        // ---- Pass A: wires 8..11 (low 4 index bits); gather applies previous layer's CNOT perm
        if (l == 0) {
#pragma unroll
            for (int j = 0; j < 16; ++j) {
                const int i = (tid << 4) | j;
                v[j] = pack2(Phi[i >> 6] * Plo[i & 63], 0.f);
            }
        } else {
#pragma unroll
            for (int j = 0; j < 16; ++j) {
                const int i = (tid << 4) | j;
                const int s = srcHi[l - 1][i >> 6] ^ srcLo[l - 1][i & 63];
                v[j] = psi[SLOT(s)];
            }
            __syncthreads();   // scattered reads must complete before overwriting
        }
        apply_gate_pk<3>(v, &gates[l][8].m00);
        apply_gate_pk<2>(v, &gates[l][9].m00);
        apply_gate_pk<1>(v, &gates[l][10].m00);
        apply_gate_pk<0>(v, &gates[l][11].m00);
#pragma unroll
        for (int j = 0; j < 16; ++j) psi[SLOT((tid << 4) | j)] = v[j];
        __syncthreads();

        // ---- Pass B: wires 4..7 (index bits 7..4)
#pragma unroll
        for (int j = 0; j < 16; ++j) {
            const int i = ((tid & 0xF0) << 4) | (j << 4) | (tid & 15);
            v[j] = psi[SLOT(i)];
        }
        apply_gate_pk<3>(v, &gates[l][4].m00);
        apply_gate_pk<2>(v, &gates[l][5].m00);
        apply_gate_pk<1>(v, &gates[l][6].m00);
        apply_gate_pk<0>(v, &gates[l][7].m00);
#pragma unroll
        for (int j = 0; j < 16; ++j) {
            const int i = ((tid & 0xF0) << 4) | (j << 4) | (tid & 15);
            psi[SLOT(i)] = v[j];
        }
        __syncthreads();

        // ---- Pass C: wires 0..3 (index bits 11..8)
#pragma unroll
        for (int j = 0; j < 16; ++j) {
            const int i = (j << 8) | tid;
            v[j] = psi[SLOT(i)];
        }
        apply_gate_pk<3>(v, &gates[l][0].m00);
        apply_gate_pk<2>(v, &gates[l][1].m00);
        apply_gate_pk<1>(v, &gates[l][2].m00);
        apply_gate_pk<0>(v, &gates[l][3].m00);
#pragma unroll
        for (int j = 0; j < 16; ++j) {
            const int i = (j << 8) | tid;
            psi[SLOT(i)] = v[j];
        }
        __syncthreads();
    }

    // ---------- Readout: final CNOT perm fused into gather; probs * signed-weight table ----------
    float acc = 0.f;
#pragma unroll
    for (int j = 0; j < 16; ++j) {
        const int i = (tid << 4) | j;
        const int s = srcHi[NL - 1][i >> 6] ^ srcLo[NL - 1][i & 63];
        const ull q = psi[SLOT(s)];
        const float re = __uint_as_float((unsigned)q);
        const float im = __uint_as_float((unsigned)(q >> 32));
        acc = fmaf(fmaf(re, re, im * im), Thi[i >> 6] + Tlo[i & 63], acc);
    }
#pragma unroll
    for (int o = 16; o; o >>= 1) acc += __shfl_xor_sync(0xFFFFFFFFu, acc, o);
    if ((tid & 31) == 0) red[tid >> 5] = acc;
    __syncthreads();
    if (tid == 0) {
        float s = 0.f;
#pragma unroll
        for (int k = 0; k < TPB / 32; ++k) s += red[k];
        out[bidx] = s + bias_p[0];
    }
}

extern "C" void kernel_launch(void* const* d_in, const int* in_sizes, int n_in,
                              void* d_out, int out_size)
{
    const float* x       = (const float*)d_in[0];
    const float* weights = (const float*)d_in[1];
    const float* W       = (const float*)d_in[2];
    const float* b       = (const float*)d_in[3];
    float* out = (float*)d_out;
    quantum_kernel<<<512, TPB>>>(x, weights, W, b, out);
}

// round 7
// speedup vs baseline: 1.8627x; 1.8627x over previous
#include <cuda_runtime.h>

#define NQ   12
#define DIM  4096
#define NL   6
#define TPB  256

// padded smem slot to avoid bank conflicts in the stride-16 pass
#define SLOT(i) ((i) + ((i) >> 4))

__device__ __forceinline__ float2 cmul(const float2 a, const float2 b) {
    float2 r;
    r.x = fmaf(a.x, b.x, -a.y * b.y);
    r.y = fmaf(a.x, b.y,  a.y * b.x);
    return r;
}

// Real Ry butterfly on pairing bit P: [c -s; s c] applied to (re,im) independently.
template <int P>
__device__ __forceinline__ void apply_ry(float2 v[16], const float c, const float s) {
#pragma unroll
    for (int j0 = 0; j0 < 16; ++j0) {
        if (j0 & (1 << P)) continue;
        const int j1 = j0 | (1 << P);
        const float2 a = v[j0], b = v[j1];
        float2 n0, n1;
        n0.x = fmaf(c, a.x, -s * b.x);
        n0.y = fmaf(c, a.y, -s * b.y);
        n1.x = fmaf(s, a.x,  c * b.x);
        n1.y = fmaf(s, a.y,  c * b.y);
        v[j0] = n0; v[j1] = n1;
    }
}

__global__ void __launch_bounds__(TPB, 3)
quantum_kernel(const float* __restrict__ x,
               const float* __restrict__ weights,
               const float* __restrict__ Wlin,
               const float* __restrict__ bias_p,
               float* __restrict__ out)
{
    __shared__ float2 psi[DIM + (DIM >> 4)];                 // ~34 KB padded state
    __shared__ float  ryc[NL][NQ], rys[NL][NQ];              // Ry cos/sin
    __shared__ float  phi05[NL][NQ], om05[NL][NQ];           // half-angles for diagonals
    __shared__ float2 DphiHi[NL][64], DphiLo[NL][64];        // Π Rz(phi) split tables
    __shared__ float2 DomHi[NL][64],  DomLo[NL][64];         // Π Rz(omega) split tables
    __shared__ unsigned short srcHi[NL][64], srcLo[NL][64];  // CNOT-layer perm (GF2 split)
    __shared__ float2 PhiC[64], PloC[64];                    // complex init tables (embed * Dphi[0])
    __shared__ float  Thi[64], Tlo[64];                      // signed-weight readout tables
    __shared__ float  cw[NQ], sw[NQ], Wv[NQ];
    __shared__ float  red[TPB / 32];

    const int tid = threadIdx.x;
    const int bidx = blockIdx.x;

    // ---------- Phase 1: embedding trig, Ry constants, diag half-angles, CNOT tables ----------
    if (tid < NQ) {
        float h = 0.5f * x[bidx * NQ + tid];
        sincosf(h, &sw[tid], &cw[tid]);
        Wv[tid] = Wlin[tid];
    }
    for (int idx = tid; idx < NL * NQ; idx += TPB) {
        const int l = idx / NQ, w = idx % NQ;
        const float* wp = weights + (l * NQ + w) * 3;
        float st, ct; sincosf(0.5f * wp[1], &st, &ct);
        ryc[l][w] = ct; rys[l][w] = st;
        phi05[l][w] = 0.5f * wp[0];
        om05[l][w]  = 0.5f * wp[2];
    }
    for (int idx = tid; idx < NL * 128; idx += TPB) {
        const int l = idx >> 7, k = idx & 127;
        const int r = l % (NQ - 1) + 1;
        unsigned v = (k < 64) ? (unsigned)k : ((unsigned)(k - 64) << 6);
        for (int w = NQ - 1; w >= 0; --w) {
            const int t = (w + r) % NQ;
            v ^= ((v >> (NQ - 1 - w)) & 1u) << (NQ - 1 - t);
        }
        if (k < 64) srcLo[l][k] = (unsigned short)v;
        else        srcHi[l][k - 64] = (unsigned short)v;
    }
    __syncthreads();

    // ---------- Phase 2: diagonal phase tables. Rz(a) = diag(e^{-ia/2}, e^{+ia/2}) ----------
    // 1536 entries: l in [0,6), which in {phiHi, phiLo, omHi, omLo}, e in [0,64)
    for (int idx = tid; idx < NL * 4 * 64; idx += TPB) {
        const int l = idx >> 8;
        const int which = (idx >> 6) & 3;       // 0 phiHi, 1 phiLo, 2 omHi, 3 omLo
        const int e = idx & 63;
        const float* ang = (which < 2) ? &phi05[l][0] : &om05[l][0];
        const int base = (which & 1) ? 6 : 0;   // lo half covers wires 6..11
        float a = 0.f;
#pragma unroll
        for (int w = 0; w < 6; ++w) {
            const float aw = ang[base + w];
            a += ((e >> (5 - w)) & 1) ? aw : -aw;
        }
        float sn, cs; sincosf(a, &sn, &cs);
        const float2 ph = make_float2(cs, sn);
        if      (which == 0) DphiHi[l][e] = ph;
        else if (which == 1) DphiLo[l][e] = ph;
        else if (which == 2) DomHi[l][e]  = ph;
        else                 DomLo[l][e]  = ph;
    }
    __syncthreads();

    // ---------- Phase 3: complex init tables (embedding product * layer-0 phi diag), readout tables ----------
    if (tid < 64) {
        const int j = tid;
        float ph = 1.f, pl = 1.f, th = 0.f, tl = 0.f;
#pragma unroll
        for (int w = 0; w < 6; ++w) {
            const int b = (j >> (5 - w)) & 1;
            ph *= b ? sw[w] : cw[w];
            th += b ? -Wv[w] : Wv[w];
            pl *= b ? sw[6 + w] : cw[6 + w];
            tl += b ? -Wv[6 + w] : Wv[6 + w];
        }
        PhiC[j] = make_float2(ph * DphiHi[0][j].x, ph * DphiHi[0][j].y);
        PloC[j] = make_float2(pl * DphiLo[0][j].x, pl * DphiLo[0][j].y);
        Thi[j] = th; Tlo[j] = tl;
    }
    __syncthreads();

    // ---------- Circuit: per layer: gather(C_{l-1} + Dphi_l) -> 12 Ry in 3 passes -> scatter(Dom_l) ----------
    float2 v[16];
    for (int l = 0; l < NL; ++l) {
        // ---- Pass A gather: wires 8..11 (low 4 index bits)
        if (l == 0) {
#pragma unroll
            for (int j = 0; j < 16; ++j) {
                const int i = (tid << 4) | j;
                v[j] = cmul(PhiC[i >> 6], PloC[i & 63]);
            }
        } else {
#pragma unroll
            for (int j = 0; j < 16; ++j) {
                const int i = (tid << 4) | j;
                const int s = srcHi[l - 1][i >> 6] ^ srcLo[l - 1][i & 63];
                const float2 d = cmul(DphiHi[l][i >> 6], DphiLo[l][i & 63]);
                v[j] = cmul(d, psi[SLOT(s)]);
            }
            __syncthreads();   // scattered reads must complete before overwriting
        }
        apply_ry<3>(v, ryc[l][8],  rys[l][8]);
        apply_ry<2>(v, ryc[l][9],  rys[l][9]);
        apply_ry<1>(v, ryc[l][10], rys[l][10]);
        apply_ry<0>(v, ryc[l][11], rys[l][11]);
#pragma unroll
        for (int j = 0; j < 16; ++j) psi[SLOT((tid << 4) | j)] = v[j];
        __syncthreads();

        // ---- Pass B: wires 4..7 (index bits 7..4)
#pragma unroll
        for (int j = 0; j < 16; ++j) {
            const int i = ((tid & 0xF0) << 4) | (j << 4) | (tid & 15);
            v[j] = psi[SLOT(i)];
        }
        apply_ry<3>(v, ryc[l][4], rys[l][4]);
        apply_ry<2>(v, ryc[l][5], rys[l][5]);
        apply_ry<1>(v, ryc[l][6], rys[l][6]);
        apply_ry<0>(v, ryc[l][7], rys[l][7]);
#pragma unroll
        for (int j = 0; j < 16; ++j) {
            const int i = ((tid & 0xF0) << 4) | (j << 4) | (tid & 15);
            psi[SLOT(i)] = v[j];
        }
        __syncthreads();

        // ---- Pass C: wires 0..3 (index bits 11..8); scatter applies omega diagonal
#pragma unroll
        for (int j = 0; j < 16; ++j) {
            const int i = (j << 8) | tid;
            v[j] = psi[SLOT(i)];
        }
        apply_ry<3>(v, ryc[l][0], rys[l][0]);
        apply_ry<2>(v, ryc[l][1], rys[l][1]);
        apply_ry<1>(v, ryc[l][2], rys[l][2]);
        apply_ry<0>(v, ryc[l][3], rys[l][3]);
        if (l < NL - 1) {
            // apply Dom_l at scatter; final layer's omega diagonal is a pure phase -> dropped
#pragma unroll
            for (int j = 0; j < 16; ++j) {
                const int i = (j << 8) | tid;
                const float2 d = cmul(DomHi[l][i >> 6], DomLo[l][i & 63]);
                psi[SLOT(i)] = cmul(d, v[j]);
            }
        } else {
#pragma unroll
            for (int j = 0; j < 16; ++j) {
                const int i = (j << 8) | tid;
                psi[SLOT(i)] = v[j];
            }
        }
        __syncthreads();
    }

    // ---------- Readout: final CNOT perm fused into gather; probs * signed-weight table ----------
    float acc = 0.f;
#pragma unroll
    for (int j = 0; j < 16; ++j) {
        const int i = (tid << 4) | j;
        const int s = srcHi[NL - 1][i >> 6] ^ srcLo[NL - 1][i & 63];
        const float2 a = psi[SLOT(s)];
        acc = fmaf(fmaf(a.x, a.x, a.y * a.y), Thi[i >> 6] + Tlo[i & 63], acc);
    }
#pragma unroll
    for (int o = 16; o; o >>= 1) acc += __shfl_xor_sync(0xFFFFFFFFu, acc, o);
    if ((tid & 31) == 0) red[tid >> 5] = acc;
    __syncthreads();
    if (tid == 0) {
        float s = 0.f;
#pragma unroll
        for (int k = 0; k < TPB / 32; ++k) s += red[k];
        out[bidx] = s + bias_p[0];
    }
}

extern "C" void kernel_launch(void* const* d_in, const int* in_sizes, int n_in,
                              void* d_out, int out_size)
{
    const float* x       = (const float*)d_in[0];
    const float* weights = (const float*)d_in[1];
    const float* W       = (const float*)d_in[2];
    const float* b       = (const float*)d_in[3];
    float* out = (float*)d_out;
    quantum_kernel<<<512, TPB>>>(x, weights, W, b, out);
}